// round 16
// baseline (speedup 1.0000x reference)
#include <cuda_runtime.h>
#include <math.h>
#include <stdint.h>

// ---------------------------------------------------------------------------
// Problem constants
//   feat[1,128,128,128] lr_guide[1,128,128,128] hr_guide[1,128,256,256]
//   W1[386,256] b1[256] W2[256,128] b2[128] W3[128,32] b3[32]
//   out [1,32,256,256] fp32
// ---------------------------------------------------------------------------
#define H_LR 128
#define W_LR 128
#define NPIX_LR (H_LR * W_LR)        // 16384
#define H_HR 256
#define W_HR 256
#define NPTS (H_HR * W_HR)           // 65536

typedef unsigned long long ull;

// ---- packed fp32x2 helpers (FFMA2 path) -----------------------------------
__device__ __forceinline__ ull pack2(float lo, float hi) {
    ull r; asm("mov.b64 %0, {%1,%2};" : "=l"(r) : "f"(lo), "f"(hi)); return r;
}
__device__ __forceinline__ ull fma2(ull a, ull b, ull c) {
    ull d; asm("fma.rn.f32x2 %0, %1, %2, %3;" : "=l"(d) : "l"(a), "l"(b), "l"(c));
    return d;
}
__device__ __forceinline__ float2 unpack2(ull v) {
    float2 f; asm("mov.b64 {%0,%1}, %2;" : "=f"(f.x), "=f"(f.y) : "l"(v)); return f;
}

// ---- cp.async helpers -----------------------------------------------------
__device__ __forceinline__ uint32_t smem_u32(const void* p) {
    uint32_t a;
    asm("{ .reg .u64 t; cvta.to.shared.u64 t, %1; cvt.u32.u64 %0, t; }"
        : "=r"(a) : "l"(p));
    return a;
}
__device__ __forceinline__ void cp16(uint32_t dst, const void* src) {
    asm volatile("cp.async.ca.shared.global [%0], [%1], 16;"
                 :: "r"(dst), "l"(src));
}
#define CP_COMMIT() asm volatile("cp.async.commit_group;" ::: "memory")
#define CP_WAIT(n)  asm volatile("cp.async.wait_group %0;" :: "n"(n) : "memory")

// 16B-unit XOR swizzle: distinct bank-quads within an 8-thread LDS phase
__device__ __forceinline__ int swz(int u) { return u ^ ((u >> 3) & 7); }

// Scratch (device globals: allocation-free per harness rules)
__device__ float g_h1f[NPIX_LR * 256];   // layer1 featc part per LR pixel (16 MB)
__device__ float g_h1g[NPTS * 256];      // layer1 guide part (+b1) per HR point
__device__ float g_w2d[256 * 256];       // W2 with each value duplicated {w,w}

// ---------------------------------------------------------------------------
// Merged layer-1 GEMMs + W2-duplication prep, one launch:
//   blocks [0,256):      h1f = featc_T @ W1[0:256,:]
//   blocks [256,1280):   h1g = hr_T @ W1[256:384,:] + b1
//   blocks [1280,1312):  g_w2d[k][2n] = g_w2d[k][2n+1] = W2[k][n]
// ---------------------------------------------------------------------------
__global__ __launch_bounds__(256, 2) void gemm_l1_merged(
    const float* __restrict__ lr,
    const float* __restrict__ ft,
    const float* __restrict__ hrg,
    const float* __restrict__ W1,
    const float* __restrict__ b1,
    const float* __restrict__ W2,
    float* __restrict__ h1f,
    float* __restrict__ h1g)
{
    __shared__ float As[4][2048];
    __shared__ float Bs[4][2048];

    const int tid = threadIdx.x;
    const int tx = tid & 15, ty = tid >> 4;

    if (blockIdx.x >= 1280) {             // W2 duplication prep
        int s = (blockIdx.x - 1280) * 1024 + tid * 4;   // 0..32767
        float4 w = *(const float4*)&W2[s];
        int k = s >> 7, n = s & 127;
        float* dst = g_w2d + k * 256 + 2 * n;
        *(float4*)&dst[0] = make_float4(w.x, w.x, w.y, w.y);
        *(float4*)&dst[4] = make_float4(w.z, w.z, w.w, w.w);
        return;
    }

    const float *img0, *img1, *W;
    float* outp;
    int M, K, mt, nt, addb1;
    {
        int bx = blockIdx.x;
        if (bx < 256) {                   // K1 (longer blocks, scheduled first)
            img0 = lr; img1 = ft; W = W1;
            M = NPIX_LR; K = 256; addb1 = 0;
            mt = bx >> 1; nt = bx & 1;
            outp = h1f;
        } else {                          // K2
            bx -= 256;
            img0 = hrg; img1 = nullptr; W = W1 + 256 * 256;
            M = NPTS; K = 128; addb1 = 1;
            mt = bx >> 1; nt = bx & 1;
            outp = h1g;
        }
    }
    const int m0 = mt * 128;
    const int n0 = nt * 128;

    const int ch = tid >> 4;           // staging channel within 16-chunk
    const int lane = tid & 15;         // staging lane (8 floats)
    const int pu0 = swz(2 * lane), pu1 = swz(2 * lane + 1);
    const uint32_t aSb = smem_u32(As);
    const uint32_t bSb = smem_u32(Bs);

    ull acc[4][8];
#pragma unroll
    for (int i = 0; i < 4; i++)
#pragma unroll
        for (int j = 0; j < 8; j++) acc[i][j] = pack2(0.f, 0.f);

    auto stage = [&](int buf, int c) {
        const float* sA = (img1 != nullptr && c >= 128)
                          ? (img1 + (c - 128) * M) : (img0 + c * M);
        uint32_t ad = aSb + buf * 8192 + ch * 512;
        cp16(ad + pu0 * 16, sA + m0 + lane * 8);
        cp16(ad + pu1 * 16, sA + m0 + lane * 8 + 4);
        const float* sB = W + c * 256 + n0;
        uint32_t bd = bSb + buf * 8192 + ch * 512;
        cp16(bd + pu0 * 16, sB + lane * 8);
        cp16(bd + pu1 * 16, sB + lane * 8 + 4);
    };

    const int nk = K >> 4;                 // 16 (K1) or 8 (K2)
    stage(0, ch);           CP_COMMIT();
    stage(1, 16 + ch);      CP_COMMIT();
    stage(2, 32 + ch);      CP_COMMIT();

    const int ua0 = swz(2 * ty), ua1 = swz(2 * ty + 1);
    const int ub0 = swz(2 * tx), ub1 = swz(2 * tx + 1);

    for (int i = 0; i < nk; i++) {
        int rem = nk - 1 - i;              // chunks still to consume after i
        if (rem >= 2)      { CP_WAIT(2); }
        else if (rem == 1) { CP_WAIT(1); }
        else               { CP_WAIT(0); }
        __syncthreads();                   // all threads done with buf (i-1)%4
        if (i + 3 < nk) { stage((i + 3) & 3, (i + 3) * 16 + ch); CP_COMMIT(); }
        const float* Ac = As[0] + (i & 3) * 2048;
        const float* Bc = Bs[0] + (i & 3) * 2048;
#pragma unroll
        for (int kk = 0; kk < 16; kk++) {
            ulonglong2 aA = *(const ulonglong2*)&Ac[kk * 128 + ua0 * 4];
            ulonglong2 aB2 = *(const ulonglong2*)&Ac[kk * 128 + ua1 * 4];
            ull a_pk[4] = {aA.x, aA.y, aB2.x, aB2.y};
            float4 bv0 = *(const float4*)&Bc[kk * 128 + ub0 * 4];
            float4 bv1 = *(const float4*)&Bc[kk * 128 + ub1 * 4];
            ull b_pk[8];
            b_pk[0] = pack2(bv0.x, bv0.x); b_pk[1] = pack2(bv0.y, bv0.y);
            b_pk[2] = pack2(bv0.z, bv0.z); b_pk[3] = pack2(bv0.w, bv0.w);
            b_pk[4] = pack2(bv1.x, bv1.x); b_pk[5] = pack2(bv1.y, bv1.y);
            b_pk[6] = pack2(bv1.z, bv1.z); b_pk[7] = pack2(bv1.w, bv1.w);
#pragma unroll
            for (int p = 0; p < 4; p++)
#pragma unroll
                for (int j = 0; j < 8; j++)
                    acc[p][j] = fma2(a_pk[p], b_pk[j], acc[p][j]);
        }
    }

    // epilogue: optional +b1 (K2 path), then 128x128 tile store
    float4 bb0 = make_float4(0.f, 0.f, 0.f, 0.f);
    float4 bb1 = make_float4(0.f, 0.f, 0.f, 0.f);
    if (addb1) {
        bb0 = *(const float4*)&b1[n0 + tx * 8];
        bb1 = *(const float4*)&b1[n0 + tx * 8 + 4];
    }
#pragma unroll
    for (int p = 0; p < 4; p++) {
        float2 u[8];
#pragma unroll
        for (int j = 0; j < 8; j++) u[j] = unpack2(acc[p][j]);
        float* r0 = outp + (size_t)(m0 + ty * 8 + 2 * p) * 256 + n0 + tx * 8;
        float* r1 = r0 + 256;
        *(float4*)r0       = make_float4(u[0].x + bb0.x, u[1].x + bb0.y,
                                         u[2].x + bb0.z, u[3].x + bb0.w);
        *(float4*)(r0 + 4) = make_float4(u[4].x + bb1.x, u[5].x + bb1.y,
                                         u[6].x + bb1.z, u[7].x + bb1.w);
        *(float4*)r1       = make_float4(u[0].y + bb0.x, u[1].y + bb0.y,
                                         u[2].y + bb0.z, u[3].y + bb0.w);
        *(float4*)(r1 + 4) = make_float4(u[4].y + bb1.x, u[5].y + bb1.y,
                                         u[6].y + bb1.z, u[7].y + bb1.w);
    }
}

// ---------------------------------------------------------------------------
// Fused tail with pre-duplicated W2 (zero dup-MOVs in the inner loop):
// per kk = 2 LDS.128 (A, packed rows) + 4 LDS.128 (B, pre-packed pairs)
//        + 32 FFMA2  (38 issue slots vs 44 before).
// hg is cp.async-staged per 32-k chunk (double-buffered, one chunk ahead).
//
// smem byte map (106112 total):
//   phase A: As @0 (16896), Bsd0 @16896 (32768), Bsd1 @49664 (32768),
//            hgc0 @82432 (4608, [pt][36]), hgc1 @87040 (4608)  end 91648
//   phase B (phase A dead): A3 @0 (67584, swz units),
//            W3s @67584 (16384), C3s @83968 (16896)            end 100864
//   persist @100864: w384 1024 | w385 @101888 | b2s @102912 512 |
//     b3s @103424 128 | rely @103552 512 | relx @104064 512 | gcs @104576 512 |
//     wq @105088 512 | nbr @105600 512                         end 106112
// ---------------------------------------------------------------------------
#define TAIL_SMEM_BYTES 106112

__global__ __launch_bounds__(256, 2) void fused_tail(
    const float* __restrict__ feat,
    const float* __restrict__ W1,
    const float* __restrict__ b2,
    const float* __restrict__ W3,
    const float* __restrict__ b3,
    float* __restrict__ out)
{
    extern __shared__ char smem[];
    float* As    = (float*)(smem);            // [kk][r] pitch 132 (phase A)
    float* Bsd0  = (float*)(smem + 16896);    // [kk][256] dup pairs, swz units
    float* Bsd1  = (float*)(smem + 49664);    // buffer 1
    float* hgc0  = (float*)(smem + 82432);    // [pt][36] hg chunk, buffer 0
    float* hgc1  = (float*)(smem + 87040);    // buffer 1
    float* A3    = (float*)(smem);            // [k2][132], swz units (phase B)
    float* W3s   = (float*)(smem + 67584);    // [k2][32] (phase B, staged late)
    float* C3s   = (float*)(smem + 83968);    // [r][33] (phase B)
    float* w384s = (float*)(smem + 100864);
    float* w385s = (float*)(smem + 101888);
    float* b2s   = (float*)(smem + 102912);
    float* b3s   = (float*)(smem + 103424);
    float* rely  = (float*)(smem + 103552);
    float* relx  = (float*)(smem + 104064);
    float* gcs   = (float*)(smem + 104576);
    float* wq    = (float*)(smem + 105088);
    int*   nbr   = (int*)  (smem + 105600);

    const int tid = threadIdx.x;
    const int p0  = blockIdx.x * 32;
    const int Y   = p0 >> 8;
    const int Xb  = p0 & 255;
    const uint32_t bsd0_u = smem_u32(Bsd0);
    const uint32_t bsd1_u = smem_u32(Bsd1);
    const uint32_t hgc0_u = smem_u32(hgc0);
    const uint32_t hgc1_u = smem_u32(hgc1);

    // cp.async stage of dup-W2 chunk c into buffer (c&1), swizzled units
    auto stageB = [&](int c) {
        uint32_t bb = (c & 1) ? bsd1_u : bsd0_u;
        const int k0 = c * 32;
#pragma unroll
        for (int i = 0; i < 8; i++) {
            int e = tid + 256 * i;            // 2048 float4 units
            int kk = e >> 6, u = e & 63;
            cp16(bb + kk * 1024 + swz(u) * 16,
                 g_w2d + (k0 + kk) * 256 + u * 4);
        }
    };
    // cp.async stage of hg chunk c (32 pts x 32 k) into buffer (c&1)
    auto stageH = [&](int c) {
        uint32_t hb = (c & 1) ? hgc1_u : hgc0_u;
        int pt = tid >> 3, kq = (tid & 7) * 4;
        cp16(hb + (pt * 36 + kq) * 4,
             g_h1g + (size_t)(p0 + pt) * 256 + c * 32 + kq);
    };

    // prologue: chunk 0 of both in flight ASAP (overlaps all setup below)
    stageB(0); stageH(0); CP_COMMIT();

    // persist loads (regions disjoint from phase A buffers)
    w384s[tid] = W1[384 * 256 + tid];
    w385s[tid] = W1[385 * 256 + tid];
    if (tid < 128) b2s[tid] = b2[tid];
    if (tid < 32)  b3s[tid] = b3[tid];

    // per-row metadata + gating dots
    if (tid < 128) {
        int pt = tid >> 2, q = tid & 3;
        int X = Xb + pt;
        int vx = (q & 2) ? 1 : -1;        // perturbs Y (H axis)
        int vy = (q & 1) ? 1 : -1;        // perturbs X (W axis)
        int iy = (Y + vx) >> 1;           // exact nearest-sample reduction
        int ix = (X + vy) >> 1;
        bool ok = ((unsigned)iy < (unsigned)H_LR) && ((unsigned)ix < (unsigned)W_LR);
        int np = iy * W_LR + ix;
        nbr[tid]  = ok ? np : -1;
        rely[tid] = ok ? ((float)(Y - 2 * iy) - 0.5f) : ((float)Y + 0.5f - 128.0f);
        relx[tid] = ok ? ((float)(X - 2 * ix) - 0.5f) : ((float)X + 0.5f - 128.0f);
        float g = 0.f;
        if (ok) {
            int bp = (Y >> 1) * W_LR + (X >> 1);
#pragma unroll
            for (int c = 0; c < 3; c++)
                g = fmaf(feat[(124 + c) * NPIX_LR + bp],
                         feat[(124 + c) * NPIX_LR + np], g);
        }
        gcs[tid] = g;
    }
    __syncthreads();                      // gcs + nbr/rel visible

    if (tid < 32) {
        float g0 = gcs[tid * 4 + 0], g1 = gcs[tid * 4 + 1];
        float g2 = gcs[tid * 4 + 2], g3 = gcs[tid * 4 + 3];
        float m = fmaxf(fmaxf(g0, g1), fmaxf(g2, g3));
        float e0 = expf(g0 - m), e1 = expf(g1 - m), e2 = expf(g2 - m), e3 = expf(g3 - m);
        float inv = 1.0f / (e0 + e1 + e2 + e3);
        wq[tid * 4 + 0] = e0 * inv;
        wq[tid * 4 + 1] = e1 * inv;
        wq[tid * 4 + 2] = e2 * inv;
        wq[tid * 4 + 3] = e3 * inv;
    }

    // As-build thread mapping: one row per thread, half the k-chunk
    const int rB  = tid & 127;            // build row (warp spans 32 rows)
    const int khB = tid >> 7;             // k half (16 k's of the 32-chunk)
    const float ryB = rely[rB], rxB = relx[rB];
    const int nbB = nbr[rB];

    float4 pf[4];                          // prefetched g_h1f half-chunk
#pragma unroll
    for (int j = 0; j < 4; j++) pf[j] = make_float4(0.f, 0.f, 0.f, 0.f);
    if (nbB >= 0) {
        const float* fr = g_h1f + nbB * 256 + khB * 16;
#pragma unroll
        for (int j = 0; j < 4; j++) pf[j] = *(const float4*)&fr[j * 4];
    }

    // ---- layer 2: 8 chunks of K=32, dup-B (no inner MOVs) ----
    const int tx = tid & 15, ty = tid >> 4;
    int ubd[4];                            // dup-B read units (float offsets)
#pragma unroll
    for (int j = 0; j < 4; j++) ubd[j] = swz(4 * tx + j) * 4;
    ull acc[4][8];
#pragma unroll
    for (int i = 0; i < 4; i++)
#pragma unroll
        for (int j = 0; j < 8; j++) acc[i][j] = pack2(0.f, 0.f);

    for (int c = 0; c < 8; c++) {
        const int k0 = c * 32;
        CP_WAIT(0);                       // Bsd[c&1] + hgc[c&1] landed
        __syncthreads();                  // visible; reads of (c-1) bufs done
        // build relu(h1) chunk into As from the staged hg chunk
        {
            const float* hgb = (c & 1) ? hgc1 : hgc0;
            const float* hrow = hgb + (rB >> 2) * 36 + khB * 16;
#pragma unroll
            for (int j = 0; j < 4; j++) {
                float4 h = *(const float4*)&hrow[j * 4];
                float4 f = pf[j];
#pragma unroll
                for (int t = 0; t < 4; t++) {
                    int kk = khB * 16 + j * 4 + t;
                    float v = (&h.x)[t] + (&f.x)[t];
                    v = fmaf(ryB, w384s[k0 + kk], v);
                    v = fmaf(rxB, w385s[k0 + kk], v);
                    As[kk * 132 + rB] = fmaxf(v, 0.f);
                }
            }
        }
        if (c < 7) {
            stageB(c + 1); stageH(c + 1); CP_COMMIT();
            if (nbB >= 0) {               // prefetch next g_h1f half-chunk
                const float* fr = g_h1f + nbB * 256 + k0 + 32 + khB * 16;
#pragma unroll
                for (int j = 0; j < 4; j++) pf[j] = *(const float4*)&fr[j * 4];
            }
        }
        __syncthreads();                  // As visible
        const float* Bsb = (c & 1) ? Bsd1 : Bsd0;
#pragma unroll
        for (int kk = 0; kk < 32; kk++) {
            ulonglong2 aA = *(const ulonglong2*)&As[kk * 132 + ty * 8];
            ulonglong2 aB = *(const ulonglong2*)&As[kk * 132 + ty * 8 + 4];
            ull a_pk[4] = {aA.x, aA.y, aB.x, aB.y};
            const float* brow = Bsb + kk * 256;
            ulonglong2 bq0 = *(const ulonglong2*)&brow[ubd[0]];
            ulonglong2 bq1 = *(const ulonglong2*)&brow[ubd[1]];
            ulonglong2 bq2 = *(const ulonglong2*)&brow[ubd[2]];
            ulonglong2 bq3 = *(const ulonglong2*)&brow[ubd[3]];
            ull b_pk[8] = {bq0.x, bq0.y, bq1.x, bq1.y,
                           bq2.x, bq2.y, bq3.x, bq3.y};
#pragma unroll
            for (int i = 0; i < 4; i++)
#pragma unroll
                for (int j = 0; j < 8; j++)
                    acc[i][j] = fma2(a_pk[i], b_pk[j], acc[i][j]);
        }
    }
    __syncthreads();                      // layer2 done; phase A smem dead

    // stage W3 (LDG latency overlaps the A3 transpose below)
    {
        *(float4*)&W3s[tid * 4]        = *(const float4*)&W3[tid * 4];
        *(float4*)&W3s[1024 + tid * 4] = *(const float4*)&W3[1024 + tid * 4];
        *(float4*)&W3s[2048 + tid * 4] = *(const float4*)&W3[2048 + tid * 4];
        *(float4*)&W3s[3072 + tid * 4] = *(const float4*)&W3[3072 + tid * 4];
    }

    // relu(l2 + b2) -> A3 transposed [k2][r], 16B units swizzled by (k2>>3)&7
    // NOTE: thread's 8 columns are now tx*8..+7 (pairs 2u..2u+1 of units
    // 4tx..4tx+3) — identical column set to before, so this epilogue and
    // everything after is unchanged.
#pragma unroll
    for (int j = 0; j < 8; j++) {
        int k2 = tx * 8 + j;
        int sw = (k2 >> 3) & 7;
        float bb = b2s[k2];
#pragma unroll
        for (int i2 = 0; i2 < 4; i2++) {
            float2 u = unpack2(acc[i2][j]);
            float2 o;
            o.x = fmaxf(u.x + bb, 0.f);
            o.y = fmaxf(u.y + bb, 0.f);
            int ro = ty * 8 + 2 * i2;            // row offset within 128
            int ur = (ro >> 2) ^ sw;             // swizzled 16B unit
            int intra = ro & 3;
            *(float2*)&A3[k2 * 132 + ur * 4 + intra] = o;
        }
    }
    __syncthreads();                      // A3 + W3s visible (BAR drains STS)

    // ---- layer 3: C3[128,32] = A3^T @ W3, k-split GEMM ----
    {
        const int kh = tid >> 7;          // k-half
        const int rem = tid & 127;
        const int rg = rem >> 3;          // rows rg*8..+7
        const int cg = rem & 7;           // cols cg*4..+3
        ull a3[4][4];
#pragma unroll
        for (int p = 0; p < 4; p++)
#pragma unroll
            for (int j = 0; j < 4; j++) a3[p][j] = pack2(0.f, 0.f);

        const float* w_base = W3s + (uint32_t)kh * 64 * 32 + cg * 4;
        for (int kt = 0; kt < 64; kt++) {
            int k2 = kh * 64 + kt;
            int sw = (k2 >> 3) & 7;
            const float* arow = A3 + k2 * 132;
            ulonglong2 aA = *(const ulonglong2*)&arow[((2 * rg) ^ sw) * 4];
            ulonglong2 aB = *(const ulonglong2*)&arow[((2 * rg + 1) ^ sw) * 4];
            float4 wv = *(const float4*)(w_base + kt * 32);
            ull w0 = pack2(wv.x, wv.x), w1 = pack2(wv.y, wv.y);
            ull w2 = pack2(wv.z, wv.z), w3v = pack2(wv.w, wv.w);
            ull ap[4] = {aA.x, aA.y, aB.x, aB.y};
#pragma unroll
            for (int p = 0; p < 4; p++) {
                a3[p][0] = fma2(ap[p], w0, a3[p][0]);
                a3[p][1] = fma2(ap[p], w1, a3[p][1]);
                a3[p][2] = fma2(ap[p], w2, a3[p][2]);
                a3[p][3] = fma2(ap[p], w3v, a3[p][3]);
            }
        }
        if (kh == 1) {
#pragma unroll
            for (int p = 0; p < 4; p++)
#pragma unroll
                for (int j = 0; j < 4; j++) {
                    float2 u = unpack2(a3[p][j]);
                    C3s[(rg * 8 + 2 * p) * 33 + cg * 4 + j]     = u.x;
                    C3s[(rg * 8 + 2 * p + 1) * 33 + cg * 4 + j] = u.y;
                }
        }
        __syncthreads();
        if (kh == 0) {
#pragma unroll
            for (int p = 0; p < 4; p++)
#pragma unroll
                for (int j = 0; j < 4; j++) {
                    float2 u = unpack2(a3[p][j]);
                    C3s[(rg * 8 + 2 * p) * 33 + cg * 4 + j]     += u.x;
                    C3s[(rg * 8 + 2 * p + 1) * 33 + cg * 4 + j] += u.y;
                }
        }
        __syncthreads();
    }

    // ---- softmax blend + coalesced channel-major store ----
#pragma unroll
    for (int i = 0; i < 4; i++) {
        int idx = tid + 256 * i;
        int pt = idx & 31, n = idx >> 5;
        float s = b3s[n];                 // sum(w)=1 -> bias post-blend
#pragma unroll
        for (int q = 0; q < 4; q++)
            s = fmaf(wq[pt * 4 + q], C3s[(pt * 4 + q) * 33 + n], s);
        out[n * NPTS + p0 + pt] = s;
    }
}

// ---------------------------------------------------------------------------
extern "C" void kernel_launch(void* const* d_in, const int* in_sizes, int n_in,
                              void* d_out, int out_size)
{
    const float* feat     = (const float*)d_in[0];
    const float* lr_guide = (const float*)d_in[1];
    const float* hr_guide = (const float*)d_in[2];
    const float* W1       = (const float*)d_in[3];
    const float* b1       = (const float*)d_in[4];
    const float* W2       = (const float*)d_in[5];
    const float* b2       = (const float*)d_in[6];
    const float* W3       = (const float*)d_in[7];
    const float* b3       = (const float*)d_in[8];
    float* out = (float*)d_out;

    void* h1f_p = nullptr;
    void* h1g_p = nullptr;
    cudaGetSymbolAddress(&h1f_p, g_h1f);
    cudaGetSymbolAddress(&h1g_p, g_h1g);

    // merged layer-1 GEMMs + W2-dup prep: 256 + 1024 + 32 blocks
    gemm_l1_merged<<<1312, 256>>>(lr_guide, feat, hr_guide, W1, b1, W2,
                                  (float*)h1f_p, (float*)h1g_p);

    // fused tail
    {
        cudaFuncSetAttribute(fused_tail, cudaFuncAttributeMaxDynamicSharedMemorySize,
                             TAIL_SMEM_BYTES);
        fused_tail<<<NPTS / 32, 256, TAIL_SMEM_BYTES>>>(
            feat, W1, b2, W3, b3, out);
    }
}

// round 17
// speedup vs baseline: 1.2159x; 1.2159x over previous
#include <cuda_runtime.h>
#include <math.h>
#include <stdint.h>

// ---------------------------------------------------------------------------
// Problem constants
//   feat[1,128,128,128] lr_guide[1,128,128,128] hr_guide[1,128,256,256]
//   W1[386,256] b1[256] W2[256,128] b2[128] W3[128,32] b3[32]
//   out [1,32,256,256] fp32
// ---------------------------------------------------------------------------
#define H_LR 128
#define W_LR 128
#define NPIX_LR (H_LR * W_LR)        // 16384
#define H_HR 256
#define W_HR 256
#define NPTS (H_HR * W_HR)           // 65536

typedef unsigned long long ull;

// ---- packed fp32x2 helpers (FFMA2 path) -----------------------------------
__device__ __forceinline__ ull pack2(float lo, float hi) {
    ull r; asm("mov.b64 %0, {%1,%2};" : "=l"(r) : "f"(lo), "f"(hi)); return r;
}
__device__ __forceinline__ ull fma2(ull a, ull b, ull c) {
    ull d; asm("fma.rn.f32x2 %0, %1, %2, %3;" : "=l"(d) : "l"(a), "l"(b), "l"(c));
    return d;
}
__device__ __forceinline__ float2 unpack2(ull v) {
    float2 f; asm("mov.b64 {%0,%1}, %2;" : "=f"(f.x), "=f"(f.y) : "l"(v)); return f;
}

// ---- cp.async helpers -----------------------------------------------------
__device__ __forceinline__ uint32_t smem_u32(const void* p) {
    uint32_t a;
    asm("{ .reg .u64 t; cvta.to.shared.u64 t, %1; cvt.u32.u64 %0, t; }"
        : "=r"(a) : "l"(p));
    return a;
}
__device__ __forceinline__ void cp16(uint32_t dst, const void* src) {
    asm volatile("cp.async.ca.shared.global [%0], [%1], 16;"
                 :: "r"(dst), "l"(src));
}
#define CP_COMMIT() asm volatile("cp.async.commit_group;" ::: "memory")
#define CP_WAIT(n)  asm volatile("cp.async.wait_group %0;" :: "n"(n) : "memory")

// 16B-unit XOR swizzle: distinct bank-quads within an 8-thread LDS phase
__device__ __forceinline__ int swz(int u) { return u ^ ((u >> 3) & 7); }

// Scratch (device globals: allocation-free per harness rules)
__device__ float g_h1f[NPIX_LR * 256];   // layer1 featc part per LR pixel (16 MB)
__device__ float g_h1g[NPTS * 256];      // layer1 guide part (+b1) per HR point

// ---------------------------------------------------------------------------
// Merged layer-1 GEMMs, one launch:
//   blocks [0,256):    h1f[16384,256] = featc_T @ W1[0:256,:]
//   blocks [256,1280): h1g[65536,256] = hr_T    @ W1[256:384,:] + b1
// BM=128, BN=128, BK=16, 256 threads, 8x8/thread (f32x2),
// 4-stage cp.async pipeline, XOR-swizzled smem units.
// ---------------------------------------------------------------------------
__global__ __launch_bounds__(256, 2) void gemm_l1_merged(
    const float* __restrict__ lr,
    const float* __restrict__ ft,
    const float* __restrict__ hrg,
    const float* __restrict__ W1,
    const float* __restrict__ b1,
    float* __restrict__ h1f,
    float* __restrict__ h1g)
{
    __shared__ float As[4][2048];
    __shared__ float Bs[4][2048];

    const int tid = threadIdx.x;
    const int tx = tid & 15, ty = tid >> 4;

    const float *img0, *img1, *W;
    float* outp;
    int M, K, mt, nt, addb1;
    {
        int bx = blockIdx.x;
        if (bx < 256) {                   // K1 (longer blocks, scheduled first)
            img0 = lr; img1 = ft; W = W1;
            M = NPIX_LR; K = 256; addb1 = 0;
            mt = bx >> 1; nt = bx & 1;
            outp = h1f;
        } else {                          // K2
            bx -= 256;
            img0 = hrg; img1 = nullptr; W = W1 + 256 * 256;
            M = NPTS; K = 128; addb1 = 1;
            mt = bx >> 1; nt = bx & 1;
            outp = h1g;
        }
    }
    const int m0 = mt * 128;
    const int n0 = nt * 128;

    const int ch = tid >> 4;           // staging channel within 16-chunk
    const int lane = tid & 15;         // staging lane (8 floats)
    const int pu0 = swz(2 * lane), pu1 = swz(2 * lane + 1);
    const uint32_t aSb = smem_u32(As);
    const uint32_t bSb = smem_u32(Bs);

    ull acc[4][8];
#pragma unroll
    for (int i = 0; i < 4; i++)
#pragma unroll
        for (int j = 0; j < 8; j++) acc[i][j] = pack2(0.f, 0.f);

    auto stage = [&](int buf, int c) {
        const float* sA = (img1 != nullptr && c >= 128)
                          ? (img1 + (c - 128) * M) : (img0 + c * M);
        uint32_t ad = aSb + buf * 8192 + ch * 512;
        cp16(ad + pu0 * 16, sA + m0 + lane * 8);
        cp16(ad + pu1 * 16, sA + m0 + lane * 8 + 4);
        const float* sB = W + c * 256 + n0;
        uint32_t bd = bSb + buf * 8192 + ch * 512;
        cp16(bd + pu0 * 16, sB + lane * 8);
        cp16(bd + pu1 * 16, sB + lane * 8 + 4);
    };

    const int nk = K >> 4;                 // 16 (K1) or 8 (K2)
    stage(0, ch);           CP_COMMIT();
    stage(1, 16 + ch);      CP_COMMIT();
    stage(2, 32 + ch);      CP_COMMIT();

    const int ua0 = swz(2 * ty), ua1 = swz(2 * ty + 1);
    const int ub0 = swz(2 * tx), ub1 = swz(2 * tx + 1);

    for (int i = 0; i < nk; i++) {
        int rem = nk - 1 - i;              // chunks still to consume after i
        if (rem >= 2)      { CP_WAIT(2); }
        else if (rem == 1) { CP_WAIT(1); }
        else               { CP_WAIT(0); }
        __syncthreads();                   // all threads done with buf (i-1)%4
        if (i + 3 < nk) { stage((i + 3) & 3, (i + 3) * 16 + ch); CP_COMMIT(); }
        const float* Ac = As[0] + (i & 3) * 2048;
        const float* Bc = Bs[0] + (i & 3) * 2048;
#pragma unroll
        for (int kk = 0; kk < 16; kk++) {
            ulonglong2 aA = *(const ulonglong2*)&Ac[kk * 128 + ua0 * 4];
            ulonglong2 aB2 = *(const ulonglong2*)&Ac[kk * 128 + ua1 * 4];
            ull a_pk[4] = {aA.x, aA.y, aB2.x, aB2.y};
            float4 bv0 = *(const float4*)&Bc[kk * 128 + ub0 * 4];
            float4 bv1 = *(const float4*)&Bc[kk * 128 + ub1 * 4];
            ull b_pk[8];
            b_pk[0] = pack2(bv0.x, bv0.x); b_pk[1] = pack2(bv0.y, bv0.y);
            b_pk[2] = pack2(bv0.z, bv0.z); b_pk[3] = pack2(bv0.w, bv0.w);
            b_pk[4] = pack2(bv1.x, bv1.x); b_pk[5] = pack2(bv1.y, bv1.y);
            b_pk[6] = pack2(bv1.z, bv1.z); b_pk[7] = pack2(bv1.w, bv1.w);
#pragma unroll
            for (int p = 0; p < 4; p++)
#pragma unroll
                for (int j = 0; j < 8; j++)
                    acc[p][j] = fma2(a_pk[p], b_pk[j], acc[p][j]);
        }
    }

    // epilogue: optional +b1 (K2 path), then 128x128 tile store
    float4 bb0 = make_float4(0.f, 0.f, 0.f, 0.f);
    float4 bb1 = make_float4(0.f, 0.f, 0.f, 0.f);
    if (addb1) {
        bb0 = *(const float4*)&b1[n0 + tx * 8];
        bb1 = *(const float4*)&b1[n0 + tx * 8 + 4];
    }
#pragma unroll
    for (int p = 0; p < 4; p++) {
        float2 u[8];
#pragma unroll
        for (int j = 0; j < 8; j++) u[j] = unpack2(acc[p][j]);
        float* r0 = outp + (size_t)(m0 + ty * 8 + 2 * p) * 256 + n0 + tx * 8;
        float* r1 = r0 + 256;
        *(float4*)r0       = make_float4(u[0].x + bb0.x, u[1].x + bb0.y,
                                         u[2].x + bb0.z, u[3].x + bb0.w);
        *(float4*)(r0 + 4) = make_float4(u[4].x + bb1.x, u[5].x + bb1.y,
                                         u[6].x + bb1.z, u[7].x + bb1.w);
        *(float4*)r1       = make_float4(u[0].y + bb0.x, u[1].y + bb0.y,
                                         u[2].y + bb0.z, u[3].y + bb0.w);
        *(float4*)(r1 + 4) = make_float4(u[4].y + bb1.x, u[5].y + bb1.y,
                                         u[6].y + bb1.z, u[7].y + bb1.w);
    }
}

// ---------------------------------------------------------------------------
// Fused tail (R13 champion, byte-identical): 8x8 inner tile, single As with
// two barriers per chunk, cp.async-staged double-buffered Bs one chunk ahead,
// full-block hg staged via plain LDG at entry.
//
// smem byte map (106112 total):
//   phase A: As @0 (16896), Bs0 @16896 (16384), Bs1 @33280 (16384),
//            hg @49664 (32x260 = 33280)                       end 82944
//   phase B (hg dead): A3 @0 (67584, swz units),
//            W3s @67584 (16384, staged after layer-2 sync), C3s @83968 (16896)
//   persist @100864: w384 1024 | w385 @101888 | b2s @102912 512 |
//     b3s @103424 128 | rely @103552 512 | relx @104064 512 | gcs @104576 512 |
//     wq @105088 512 | nbr @105600 512                        end 106112
// ---------------------------------------------------------------------------
#define TAIL_SMEM_BYTES 106112

__global__ __launch_bounds__(256, 2) void fused_tail(
    const float* __restrict__ feat,
    const float* __restrict__ W1,
    const float* __restrict__ W2,
    const float* __restrict__ b2,
    const float* __restrict__ W3,
    const float* __restrict__ b3,
    float* __restrict__ out)
{
    extern __shared__ char smem[];
    float* As    = (float*)(smem);            // [kk][r] pitch 132 (phase A)
    float* Bs0   = (float*)(smem + 16896);    // [kk][128] swz units, buffer 0
    float* Bs1   = (float*)(smem + 33280);    // buffer 1
    float* hg    = (float*)(smem + 49664);    // [pt][260] (phase A)
    float* A3    = (float*)(smem);            // [k2][132], swz units (phase B)
    float* W3s   = (float*)(smem + 67584);    // [k2][32] (phase B, staged late)
    float* C3s   = (float*)(smem + 83968);    // [r][33] (phase B)
    float* w384s = (float*)(smem + 100864);
    float* w385s = (float*)(smem + 101888);
    float* b2s   = (float*)(smem + 102912);
    float* b3s   = (float*)(smem + 103424);
    float* rely  = (float*)(smem + 103552);
    float* relx  = (float*)(smem + 104064);
    float* gcs   = (float*)(smem + 104576);
    float* wq    = (float*)(smem + 105088);
    int*   nbr   = (int*)  (smem + 105600);

    const int tid = threadIdx.x;
    const int p0  = blockIdx.x * 32;
    const int Y   = p0 >> 8;
    const int Xb  = p0 & 255;
    const uint32_t bs0_u = smem_u32(Bs0);
    const uint32_t bs1_u = smem_u32(Bs1);

    // cp.async stage of W2 chunk c into buffer (c&1), swizzled units
    auto stageB = [&](int c) {
        uint32_t bb = (c & 1) ? bs1_u : bs0_u;
        const int k0 = c * 32;
#pragma unroll
        for (int i = 0; i < 4; i++) {
            int e = tid + 256 * i;            // 1024 float4 units
            int kk = e >> 5, u = e & 31;
            cp16(bb + kk * 512 + swz(u) * 16,
                 W2 + (k0 + kk) * 128 + u * 4);
        }
    };

    // prologue: W2 chunk 0 in flight ASAP (overlaps all setup below)
    stageB(0); CP_COMMIT();

    // persist loads (regions disjoint from phase A buffers)
    w384s[tid] = W1[384 * 256 + tid];
    w385s[tid] = W1[385 * 256 + tid];
    if (tid < 128) b2s[tid] = b2[tid];
    if (tid < 32)  b3s[tid] = b3[tid];

    // per-row metadata + gating dots
    if (tid < 128) {
        int pt = tid >> 2, q = tid & 3;
        int X = Xb + pt;
        int vx = (q & 2) ? 1 : -1;        // perturbs Y (H axis)
        int vy = (q & 1) ? 1 : -1;        // perturbs X (W axis)
        int iy = (Y + vx) >> 1;           // exact nearest-sample reduction
        int ix = (X + vy) >> 1;
        bool ok = ((unsigned)iy < (unsigned)H_LR) && ((unsigned)ix < (unsigned)W_LR);
        int np = iy * W_LR + ix;
        nbr[tid]  = ok ? np : -1;
        rely[tid] = ok ? ((float)(Y - 2 * iy) - 0.5f) : ((float)Y + 0.5f - 128.0f);
        relx[tid] = ok ? ((float)(X - 2 * ix) - 0.5f) : ((float)X + 0.5f - 128.0f);
        float g = 0.f;
        if (ok) {
            int bp = (Y >> 1) * W_LR + (X >> 1);
#pragma unroll
            for (int c = 0; c < 3; c++)
                g = fmaf(feat[(124 + c) * NPIX_LR + bp],
                         feat[(124 + c) * NPIX_LR + np], g);
        }
        gcs[tid] = g;
    }

    // stage full hg once (b1 pre-folded by producer): 32 pts x 256 k, pitch 260
#pragma unroll
    for (int i = 0; i < 8; i++) {
        int e = tid + 256 * i;            // float4 slots
        int pt = e >> 6, kq = (e & 63) * 4;
        *(float4*)&hg[pt * 260 + kq] =
            *(const float4*)&g_h1g[(p0 + pt) * 256 + kq];
    }
    __syncthreads();

    if (tid < 32) {
        float g0 = gcs[tid * 4 + 0], g1 = gcs[tid * 4 + 1];
        float g2 = gcs[tid * 4 + 2], g3 = gcs[tid * 4 + 3];
        float m = fmaxf(fmaxf(g0, g1), fmaxf(g2, g3));
        float e0 = expf(g0 - m), e1 = expf(g1 - m), e2 = expf(g2 - m), e3 = expf(g3 - m);
        float inv = 1.0f / (e0 + e1 + e2 + e3);
        wq[tid * 4 + 0] = e0 * inv;
        wq[tid * 4 + 1] = e1 * inv;
        wq[tid * 4 + 2] = e2 * inv;
        wq[tid * 4 + 3] = e3 * inv;
    }

    // As-build thread mapping: one row per thread, half the k-chunk
    const int rB  = tid & 127;            // build row (warp spans 32 rows)
    const int khB = tid >> 7;             // k half (16 k's of the 32-chunk)
    const float ryB = rely[rB], rxB = relx[rB];
    const int nbB = nbr[rB];

    float4 pf[4];                          // prefetched g_h1f half-chunk
#pragma unroll
    for (int j = 0; j < 4; j++) pf[j] = make_float4(0.f, 0.f, 0.f, 0.f);
    if (nbB >= 0) {
        const float* fr = g_h1f + nbB * 256 + khB * 16;
#pragma unroll
        for (int j = 0; j < 4; j++) pf[j] = *(const float4*)&fr[j * 4];
    }

    // ---- layer 2: 8 chunks of K=32, cp.async-staged Bs (1 chunk ahead) ----
    const int tx = tid & 15, ty = tid >> 4;
    const int ub0 = swz(2 * tx), ub1 = swz(2 * tx + 1);
    ull acc[4][8];
#pragma unroll
    for (int i = 0; i < 4; i++)
#pragma unroll
        for (int j = 0; j < 8; j++) acc[i][j] = pack2(0.f, 0.f);

    for (int c = 0; c < 8; c++) {
        const int k0 = c * 32;
        CP_WAIT(0);                       // Bs[c&1] landed (issued @ c-1)
        __syncthreads();                  // visible to all; As reads (c-1) done
        // build relu(h1) chunk into As (no gmem latency in this region)
        {
            const float* hrow = hg + (rB >> 2) * 260 + k0 + khB * 16;
#pragma unroll
            for (int j = 0; j < 4; j++) {
                float4 h = *(const float4*)&hrow[j * 4];
                float4 f = pf[j];
#pragma unroll
                for (int t = 0; t < 4; t++) {
                    int kk = khB * 16 + j * 4 + t;
                    float v = (&h.x)[t] + (&f.x)[t];
                    v = fmaf(ryB, w384s[k0 + kk], v);
                    v = fmaf(rxB, w385s[k0 + kk], v);
                    As[kk * 132 + rB] = fmaxf(v, 0.f);
                }
            }
        }
        if (c < 7) {
            stageB(c + 1); CP_COMMIT();   // hw-async into the other buffer
            if (nbB >= 0) {               // prefetch next g_h1f half-chunk
                const float* fr = g_h1f + nbB * 256 + k0 + 32 + khB * 16;
#pragma unroll
                for (int j = 0; j < 4; j++) pf[j] = *(const float4*)&fr[j * 4];
            }
        }
        __syncthreads();                  // As visible
        const float* Bsb = (c & 1) ? Bs1 : Bs0;
#pragma unroll
        for (int kk = 0; kk < 32; kk++) {
            ulonglong2 aA = *(const ulonglong2*)&As[kk * 132 + ty * 8];
            ulonglong2 aB = *(const ulonglong2*)&As[kk * 132 + ty * 8 + 4];
            ull a_pk[4] = {aA.x, aA.y, aB.x, aB.y};
            float4 bv0 = *(const float4*)&Bsb[kk * 128 + ub0 * 4];
            float4 bv1 = *(const float4*)&Bsb[kk * 128 + ub1 * 4];
            ull b_pk[8];
            b_pk[0] = pack2(bv0.x, bv0.x); b_pk[1] = pack2(bv0.y, bv0.y);
            b_pk[2] = pack2(bv0.z, bv0.z); b_pk[3] = pack2(bv0.w, bv0.w);
            b_pk[4] = pack2(bv1.x, bv1.x); b_pk[5] = pack2(bv1.y, bv1.y);
            b_pk[6] = pack2(bv1.z, bv1.z); b_pk[7] = pack2(bv1.w, bv1.w);
#pragma unroll
            for (int i = 0; i < 4; i++)
#pragma unroll
                for (int j = 0; j < 8; j++)
                    acc[i][j] = fma2(a_pk[i], b_pk[j], acc[i][j]);
        }
    }
    __syncthreads();                      // layer2 done; phase A smem dead

    // stage W3 (LDG latency overlaps the A3 transpose below)
    {
        *(float4*)&W3s[tid * 4]        = *(const float4*)&W3[tid * 4];
        *(float4*)&W3s[1024 + tid * 4] = *(const float4*)&W3[1024 + tid * 4];
        *(float4*)&W3s[2048 + tid * 4] = *(const float4*)&W3[2048 + tid * 4];
        *(float4*)&W3s[3072 + tid * 4] = *(const float4*)&W3[3072 + tid * 4];
    }

    // relu(l2 + b2) -> A3 transposed [k2][r], 16B units swizzled by (k2>>3)&7
#pragma unroll
    for (int j = 0; j < 8; j++) {
        int k2 = tx * 8 + j;
        int sw = (k2 >> 3) & 7;
        float bb = b2s[k2];
#pragma unroll
        for (int i2 = 0; i2 < 4; i2++) {
            float2 u = unpack2(acc[i2][j]);
            float2 o;
            o.x = fmaxf(u.x + bb, 0.f);
            o.y = fmaxf(u.y + bb, 0.f);
            int ro = ty * 8 + 2 * i2;            // row offset within 128
            int ur = (ro >> 2) ^ sw;             // swizzled 16B unit
            int intra = ro & 3;
            *(float2*)&A3[k2 * 132 + ur * 4 + intra] = o;
        }
    }
    __syncthreads();                      // A3 + W3s visible (BAR drains STS)

    // ---- layer 3: C3[128,32] = A3^T @ W3, k-split GEMM ----
    {
        const int kh = tid >> 7;          // k-half
        const int rem = tid & 127;
        const int rg = rem >> 3;          // rows rg*8..+7
        const int cg = rem & 7;           // cols cg*4..+3
        ull a3[4][4];
#pragma unroll
        for (int p = 0; p < 4; p++)
#pragma unroll
            for (int j = 0; j < 4; j++) a3[p][j] = pack2(0.f, 0.f);

        const float* w_base = W3s + (uint32_t)kh * 64 * 32 + cg * 4;
        for (int kt = 0; kt < 64; kt++) {
            int k2 = kh * 64 + kt;
            int sw = (k2 >> 3) & 7;
            const float* arow = A3 + k2 * 132;
            ulonglong2 aA = *(const ulonglong2*)&arow[((2 * rg) ^ sw) * 4];
            ulonglong2 aB = *(const ulonglong2*)&arow[((2 * rg + 1) ^ sw) * 4];
            float4 wv = *(const float4*)(w_base + kt * 32);
            ull w0 = pack2(wv.x, wv.x), w1 = pack2(wv.y, wv.y);
            ull w2 = pack2(wv.z, wv.z), w3v = pack2(wv.w, wv.w);
            ull ap[4] = {aA.x, aA.y, aB.x, aB.y};
#pragma unroll
            for (int p = 0; p < 4; p++) {
                a3[p][0] = fma2(ap[p], w0, a3[p][0]);
                a3[p][1] = fma2(ap[p], w1, a3[p][1]);
                a3[p][2] = fma2(ap[p], w2, a3[p][2]);
                a3[p][3] = fma2(ap[p], w3v, a3[p][3]);
            }
        }
        if (kh == 1) {
#pragma unroll
            for (int p = 0; p < 4; p++)
#pragma unroll
                for (int j = 0; j < 4; j++) {
                    float2 u = unpack2(a3[p][j]);
                    C3s[(rg * 8 + 2 * p) * 33 + cg * 4 + j]     = u.x;
                    C3s[(rg * 8 + 2 * p + 1) * 33 + cg * 4 + j] = u.y;
                }
        }
        __syncthreads();
        if (kh == 0) {
#pragma unroll
            for (int p = 0; p < 4; p++)
#pragma unroll
                for (int j = 0; j < 4; j++) {
                    float2 u = unpack2(a3[p][j]);
                    C3s[(rg * 8 + 2 * p) * 33 + cg * 4 + j]     += u.x;
                    C3s[(rg * 8 + 2 * p + 1) * 33 + cg * 4 + j] += u.y;
                }
        }
        __syncthreads();
    }

    // ---- softmax blend + coalesced channel-major store ----
#pragma unroll
    for (int i = 0; i < 4; i++) {
        int idx = tid + 256 * i;
        int pt = idx & 31, n = idx >> 5;
        float s = b3s[n];                 // sum(w)=1 -> bias post-blend
#pragma unroll
        for (int q = 0; q < 4; q++)
            s = fmaf(wq[pt * 4 + q], C3s[(pt * 4 + q) * 33 + n], s);
        out[n * NPTS + p0 + pt] = s;
    }
}

// ---------------------------------------------------------------------------
extern "C" void kernel_launch(void* const* d_in, const int* in_sizes, int n_in,
                              void* d_out, int out_size)
{
    const float* feat     = (const float*)d_in[0];
    const float* lr_guide = (const float*)d_in[1];
    const float* hr_guide = (const float*)d_in[2];
    const float* W1       = (const float*)d_in[3];
    const float* b1       = (const float*)d_in[4];
    const float* W2       = (const float*)d_in[5];
    const float* b2       = (const float*)d_in[6];
    const float* W3       = (const float*)d_in[7];
    const float* b3       = (const float*)d_in[8];
    float* out = (float*)d_out;

    void* h1f_p = nullptr;
    void* h1g_p = nullptr;
    cudaGetSymbolAddress(&h1f_p, g_h1f);
    cudaGetSymbolAddress(&h1g_p, g_h1g);

    // merged layer-1 GEMMs: 256 K1-blocks + 1024 K2-blocks
    gemm_l1_merged<<<1280, 256>>>(lr_guide, feat, hr_guide, W1, b1,
                                  (float*)h1f_p, (float*)h1g_p);

    // fused tail
    {
        cudaFuncSetAttribute(fused_tail, cudaFuncAttributeMaxDynamicSharedMemorySize,
                             TAIL_SMEM_BYTES);
        fused_tail<<<NPTS / 32, 256, TAIL_SMEM_BYTES>>>(
            feat, W1, W2, b2, W3, b3, out);
    }
}